// round 5
// baseline (speedup 1.0000x reference)
#include <cuda_runtime.h>
#include <math_constants.h>

#define BB 32
#define CC 64
#define HH 256
#define WW 256
#define HW (HH * WW)
#define TPB 256
#define HALF 8
#define INV_T 100.0f      // 1 / TEMPERATURE
#define PARTS 4           // CTAs per channel in phase 1
#define PART_F4 (HW / 4 / PARTS)   // float4 elems per part = 4096

// phase-1 partial results: one packed key per (channel, part)
__device__ unsigned long long g_keys[BB * CC * PARTS];

// monotone float -> uint transform (order-preserving for all finite floats)
__device__ __forceinline__ unsigned int f2sortable(float f) {
    unsigned int u = __float_as_uint(f);
    return u ^ ((u & 0x80000000u) ? 0xFFFFFFFFu : 0x80000000u);
}
__device__ __forceinline__ float sortable2f(unsigned int u) {
    return __uint_as_float(u ^ ((u & 0x80000000u) ? 0x80000000u : 0xFFFFFFFFu));
}

// ---------------- Phase 1: per-part argmax ----------------
__global__ __launch_bounds__(TPB)
void argmax_part_kernel(const float* __restrict__ hm)
{
    const int part = blockIdx.x & (PARTS - 1);
    const int bc   = blockIdx.x >> 2;
    const int tid  = threadIdx.x;

    const float4* __restrict__ base4 =
        (const float4*)(hm + (size_t)bc * HW) + part * PART_F4;

    float best = -CUDART_INF_F;
    int bidx = 0;   // local index within the part [0, HW/PARTS)

    #pragma unroll 4
    for (int i = tid; i < PART_F4; i += TPB) {
        float4 v = base4[i];
        if (v.x > best) { best = v.x; bidx = 4 * i + 0; }
        if (v.y > best) { best = v.y; bidx = 4 * i + 1; }
        if (v.z > best) { best = v.z; bidx = 4 * i + 2; }
        if (v.w > best) { best = v.w; bidx = 4 * i + 3; }
    }

    const int gidx = part * (HW / PARTS) + bidx;
    unsigned long long key =
        ((unsigned long long)f2sortable(best) << 32) | (unsigned int)(~gidx);

    __shared__ unsigned long long sk[TPB];
    sk[tid] = key;
    __syncthreads();

    #pragma unroll
    for (int s = TPB / 2; s > 0; s >>= 1) {
        if (tid < s) {
            unsigned long long o = sk[tid + s];
            if (o > sk[tid]) sk[tid] = o;
        }
        __syncthreads();
    }

    if (tid == 0) g_keys[blockIdx.x] = sk[0];
}

// ---------------- Phase 2: reduce parts + windowed softmax moments ----------------
__global__ __launch_bounds__(TPB)
void window_kernel(const float* __restrict__ hm, float* __restrict__ out)
{
    const int bc  = blockIdx.x;
    const int tid = threadIdx.x;
    const float* __restrict__ base = hm + (size_t)bc * HW;

    // every thread reduces the 4 part-keys (uniform, L2-cheap)
    unsigned long long key = g_keys[bc * PARTS + 0];
    #pragma unroll
    for (int p = 1; p < PARTS; ++p) {
        unsigned long long o = g_keys[bc * PARTS + p];
        if (o > key) key = o;
    }

    const float peak = sortable2f((unsigned int)(key >> 32));
    const int   idx  = (int)(~(unsigned int)key);
    const int   x0   = idx & (WW - 1);
    const int   y0   = idx >> 8;

    const int xmin = max(x0 - HALF, 0);
    const int xmax = min(x0 + HALF, WW);
    const int ymin = max(y0 - HALF, 0);
    const int ymax = min(y0 + HALF, HH);

    const int wx = tid & 15;
    const int wy = tid >> 4;
    const int x = xmin + wx;
    const int y = ymin + wy;

    // moments centered at (x0, y0) to avoid cancellation
    float e = 0.f, edx = 0.f, edy = 0.f, edxx = 0.f, edyy = 0.f, edxy = 0.f;
    if (x < xmax && y < ymax) {
        float v  = base[y * WW + x];
        e        = __expf((v - peak) * INV_T);
        float dx = (float)(x - x0);
        float dy = (float)(y - y0);
        edx  = e * dx;
        edy  = e * dy;
        edxx = e * dx * dx;
        edyy = e * dy * dy;
        edxy = e * dx * dy;
    }

    float vals[6] = { e, edx, edy, edxx, edyy, edxy };
    #pragma unroll
    for (int off = 16; off > 0; off >>= 1) {
        #pragma unroll
        for (int k = 0; k < 6; ++k)
            vals[k] += __shfl_down_sync(0xFFFFFFFFu, vals[k], off);
    }

    __shared__ float red[TPB / 32][6];
    const int warp = tid >> 5;
    const int lane = tid & 31;
    if (lane == 0) {
        #pragma unroll
        for (int k = 0; k < 6; ++k) red[warp][k] = vals[k];
    }
    __syncthreads();

    if (tid == 0) {
        float S = 0.f, Sdx = 0.f, Sdy = 0.f, Sdxx = 0.f, Sdyy = 0.f, Sdxy = 0.f;
        #pragma unroll
        for (int w = 0; w < TPB / 32; ++w) {
            S    += red[w][0];
            Sdx  += red[w][1];
            Sdy  += red[w][2];
            Sdxx += red[w][3];
            Sdyy += red[w][4];
            Sdxy += red[w][5];
        }
        float inv = 1.0f / S;
        float mdx = Sdx * inv;
        float mdy = Sdy * inv;
        float x_mean = (float)x0 + mdx;
        float y_mean = (float)y0 + mdy;
        float var_xx = Sdxx * inv - mdx * mdx;
        float var_yy = Sdyy * inv - mdy * mdy;
        float cov_xy = Sdxy * inv - mdx * mdy;

        // output layout: coords (B,C,2) | cov (B,C,2,2) | spread (B,C,1)
        out[bc * 2 + 0] = x_mean * (1.0f / (WW - 1));
        out[bc * 2 + 1] = y_mean * (1.0f / (HH - 1));

        float* covp = out + BB * CC * 2;
        covp[bc * 4 + 0] = var_xx;
        covp[bc * 4 + 1] = cov_xy;
        covp[bc * 4 + 2] = cov_xy;
        covp[bc * 4 + 3] = var_yy;

        out[BB * CC * 6 + bc] = var_xx + var_yy;
    }
}

extern "C" void kernel_launch(void* const* d_in, const int* in_sizes, int n_in,
                              void* d_out, int out_size)
{
    const float* hm = (const float*)d_in[0];
    float* out = (float*)d_out;
    argmax_part_kernel<<<BB * CC * PARTS, TPB>>>(hm);
    window_kernel<<<BB * CC, TPB>>>(hm, out);
}

// round 6
// speedup vs baseline: 1.0142x; 1.0142x over previous
#include <cuda_runtime.h>
#include <math_constants.h>

#define BB 32
#define CC 64
#define HH 256
#define WW 256
#define HW (HH * WW)
#define TPB 256
#define HALF 8
#define INV_T 100.0f      // 1 / TEMPERATURE
#define PARTS 4           // CTAs per channel
#define PART_F4 (HW / 4 / PARTS)   // float4 elems per part = 4096

// per-(channel,part) packed argmax keys + per-channel arrival counters
__device__ unsigned long long g_keys[BB * CC * PARTS];
__device__ unsigned int       g_cnt[BB * CC];   // zero-init; self-resetting

// monotone float -> uint transform (order-preserving)
__device__ __forceinline__ unsigned int f2sortable(float f) {
    unsigned int u = __float_as_uint(f);
    return u ^ ((u & 0x80000000u) ? 0xFFFFFFFFu : 0x80000000u);
}
__device__ __forceinline__ float sortable2f(unsigned int u) {
    return __uint_as_float(u ^ ((u & 0x80000000u) ? 0x80000000u : 0xFFFFFFFFu));
}

__global__ __launch_bounds__(TPB, 8)
void softargmax_fused(const float* __restrict__ hm, float* __restrict__ out)
{
    const int part = blockIdx.x & (PARTS - 1);
    const int bc   = blockIdx.x >> 2;
    const int tid  = threadIdx.x;
    const float* __restrict__ base = hm + (size_t)bc * HW;

    // ---------------- Phase 1: per-part argmax (bandwidth-bound) ----------------
    const float4* __restrict__ base4 = (const float4*)base + part * PART_F4;

    float best = -CUDART_INF_F;
    int bidx = 0;

    #pragma unroll 4
    for (int i = tid; i < PART_F4; i += TPB) {
        float4 v = base4[i];
        if (v.x > best) { best = v.x; bidx = 4 * i + 0; }
        if (v.y > best) { best = v.y; bidx = 4 * i + 1; }
        if (v.z > best) { best = v.z; bidx = 4 * i + 2; }
        if (v.w > best) { best = v.w; bidx = 4 * i + 3; }
    }

    const int gidx = part * (HW / PARTS) + bidx;
    unsigned long long key =
        ((unsigned long long)f2sortable(best) << 32) | (unsigned int)(~gidx);

    __shared__ unsigned long long sk[TPB];
    sk[tid] = key;
    __syncthreads();

    #pragma unroll
    for (int s = TPB / 2; s > 0; s >>= 1) {
        if (tid < s) {
            unsigned long long o = sk[tid + s];
            if (o > sk[tid]) sk[tid] = o;
        }
        __syncthreads();
    }

    // publish key; last CTA of this channel proceeds to phase 2
    __shared__ int amLast;
    if (tid == 0) {
        g_keys[blockIdx.x] = sk[0];
        __threadfence();                       // order key before counter
        unsigned int old = atomicAdd(&g_cnt[bc], 1u);
        amLast = (old == PARTS - 1);
        if (amLast) g_cnt[bc] = 0;             // self-reset for next replay
    }
    __syncthreads();
    if (!amLast) return;
    __threadfence();                           // acquire side

    // ---------------- Phase 2: reduce keys + windowed softmax moments ----------------
    unsigned long long k = g_keys[bc * PARTS + 0];
    #pragma unroll
    for (int p = 1; p < PARTS; ++p) {
        unsigned long long o = g_keys[bc * PARTS + p];
        if (o > k) k = o;
    }

    const float peak = sortable2f((unsigned int)(k >> 32));
    const int   idx  = (int)(~(unsigned int)k);
    const int   x0   = idx & (WW - 1);
    const int   y0   = idx >> 8;

    const int xmin = max(x0 - HALF, 0);
    const int xmax = min(x0 + HALF, WW);
    const int ymin = max(y0 - HALF, 0);
    const int ymax = min(y0 + HALF, HH);

    const int wx = tid & 15;
    const int wy = tid >> 4;
    const int x = xmin + wx;
    const int y = ymin + wy;

    // moments centered at (x0, y0) to avoid cancellation
    float e = 0.f, edx = 0.f, edy = 0.f, edxx = 0.f, edyy = 0.f, edxy = 0.f;
    if (x < xmax && y < ymax) {
        float v  = base[y * WW + x];
        e        = __expf((v - peak) * INV_T);
        float dx = (float)(x - x0);
        float dy = (float)(y - y0);
        edx  = e * dx;
        edy  = e * dy;
        edxx = e * dx * dx;
        edyy = e * dy * dy;
        edxy = e * dx * dy;
    }

    float vals[6] = { e, edx, edy, edxx, edyy, edxy };
    #pragma unroll
    for (int off = 16; off > 0; off >>= 1) {
        #pragma unroll
        for (int kk = 0; kk < 6; ++kk)
            vals[kk] += __shfl_down_sync(0xFFFFFFFFu, vals[kk], off);
    }

    __shared__ float red[TPB / 32][6];
    const int warp = tid >> 5;
    const int lane = tid & 31;
    if (lane == 0) {
        #pragma unroll
        for (int kk = 0; kk < 6; ++kk) red[warp][kk] = vals[kk];
    }
    __syncthreads();

    if (tid == 0) {
        float S = 0.f, Sdx = 0.f, Sdy = 0.f, Sdxx = 0.f, Sdyy = 0.f, Sdxy = 0.f;
        #pragma unroll
        for (int w = 0; w < TPB / 32; ++w) {
            S    += red[w][0];
            Sdx  += red[w][1];
            Sdy  += red[w][2];
            Sdxx += red[w][3];
            Sdyy += red[w][4];
            Sdxy += red[w][5];
        }
        float inv = 1.0f / S;
        float mdx = Sdx * inv;
        float mdy = Sdy * inv;
        float x_mean = (float)x0 + mdx;
        float y_mean = (float)y0 + mdy;
        float var_xx = Sdxx * inv - mdx * mdx;
        float var_yy = Sdyy * inv - mdy * mdy;
        float cov_xy = Sdxy * inv - mdx * mdy;

        // output layout: coords (B,C,2) | cov (B,C,2,2) | spread (B,C,1)
        out[bc * 2 + 0] = x_mean * (1.0f / (WW - 1));
        out[bc * 2 + 1] = y_mean * (1.0f / (HH - 1));

        float* covp = out + BB * CC * 2;
        covp[bc * 4 + 0] = var_xx;
        covp[bc * 4 + 1] = cov_xy;
        covp[bc * 4 + 2] = cov_xy;
        covp[bc * 4 + 3] = var_yy;

        out[BB * CC * 6 + bc] = var_xx + var_yy;
    }
}

extern "C" void kernel_launch(void* const* d_in, const int* in_sizes, int n_in,
                              void* d_out, int out_size)
{
    const float* hm = (const float*)d_in[0];
    float* out = (float*)d_out;
    softargmax_fused<<<BB * CC * PARTS, TPB>>>(hm, out);
}